// round 12
// baseline (speedup 1.0000x reference)
#include <cuda_runtime.h>
#include <math.h>
#include <stdint.h>

#define TOKENS     8192
#define MODEL_DIM  4096
#define PROMPT_DIM 64
#define NE         8
#define NP         4
#define THREADS    512
#define TPB        64                         // tokens per CTA (1 MB contiguous region)
#define GRID       (TOKENS / TPB)             // 128
#define NSTAGE     4
#define STAGE_FLOATS 8192                     // 2 tokens x 4096 = 32 KB
#define NST        (TPB / 2)                  // 32 stages per CTA
#define SMEM_BYTES (NSTAGE * STAGE_FLOATS * 4 + 512 * 4 + 256 * 8)  // 135,168 B

// ---- cp.async ----
__device__ __forceinline__ void cp16(uint32_t saddr, const void* g) {
    asm volatile("cp.async.cg.shared.global [%0], [%1], 16;" :: "r"(saddr), "l"(g) : "memory");
}
__device__ __forceinline__ void cp_commit() {
    asm volatile("cp.async.commit_group;" ::: "memory");
}
template <int N>
__device__ __forceinline__ void cp_wait() {
    asm volatile("cp.async.wait_group %0;" :: "n"(N) : "memory");
}
// ---- packed fp32x2 ----
__device__ __forceinline__ void ffma2(unsigned long long& d,
                                      unsigned long long a, unsigned long long b) {
    asm("fma.rn.f32x2 %0, %1, %2, %0;" : "+l"(d) : "l"(a), "l"(b));
}
__device__ __forceinline__ unsigned long long addf2(unsigned long long a,
                                                    unsigned long long b) {
    unsigned long long r;
    asm("add.rn.f32x2 %0, %1, %2;" : "=l"(r) : "l"(a), "l"(b));
    return r;
}
__device__ __forceinline__ unsigned long long dup2(float v) {
    unsigned long long r;
    asm("mov.b64 %0, {%1, %1};" : "=l"(r) : "f"(v));
    return r;
}
__device__ __forceinline__ unsigned long long pack2(float lo, float hi) {
    unsigned long long r;
    asm("mov.b64 %0, {%1, %2};" : "=l"(r) : "f"(lo), "f"(hi));
    return r;
}
__device__ __forceinline__ void unpack2(unsigned long long v, float& lo, float& hi) {
    asm("mov.b64 {%0, %1}, %2;" : "=f"(lo), "=f"(hi) : "l"(v));
}

__global__ __launch_bounds__(THREADS, 1)
void topkgate_kernel(const float* __restrict__ x,
                     const float* __restrict__ prompt,
                     const float* __restrict__ W,
                     const float* __restrict__ b,
                     float* __restrict__ out)
{
    extern __shared__ __align__(16) float smem[];
    float* stg    = smem;                                   // 4 x 8192 floats
    float* logits = smem + NSTAGE * STAGE_FLOATS;           // [64][8]
    unsigned long long* wtailp =
        (unsigned long long*)(logits + 512);                // [64 dims][4 pairs]

    const int tid  = threadIdx.x;
    const int lane = tid & 31;
    const float* xr = x + (size_t)blockIdx.x * TPB * MODEL_DIM;  // contiguous 1 MB

    const uint32_t stg_u32 = (uint32_t)__cvta_generic_to_shared(stg);

    // ---- zero logits; stage W-tail (dims 4096..4159, paired) into SMEM ----
    logits[tid] = 0.0f;
    if (tid < 256) {
        // u64 view of W: row d = 4 x u64 (pairs); tail row (4096+d), pair p
        wtailp[tid] = ((const unsigned long long*)W)[(size_t)(4096 + (tid >> 2)) * 4 + (tid & 3)];
    }

    // ---- W into registers: thread owns dims {4t..4t+3} and {2048+4t..+3} ----
    // W row d = 32 B; thread's group = 4 consecutive rows = 128 B contiguous.
    unsigned long long w0[4][4], w1[4][4];
    {
        const ulonglong2* wv2 = (const ulonglong2*)W;
#pragma unroll
        for (int k = 0; k < 4; k++) {
            ulonglong2 a0 = __ldg(&wv2[8 * tid + 2 * k]);
            ulonglong2 b0 = __ldg(&wv2[8 * tid + 2 * k + 1]);
            w0[k][0] = a0.x; w0[k][1] = a0.y; w0[k][2] = b0.x; w0[k][3] = b0.y;
            ulonglong2 a1 = __ldg(&wv2[4096 + 8 * tid + 2 * k]);
            ulonglong2 b1 = __ldg(&wv2[4096 + 8 * tid + 2 * k + 1]);
            w1[k][0] = a1.x; w1[k][1] = a1.y; w1[k][2] = b1.x; w1[k][3] = b1.y;
        }
    }

    // ---- Prologue: stages 0..2 (each: 512 thr x 4 x 16 B, per-instr conflict-free) ----
#pragma unroll
    for (int s = 0; s < NSTAGE - 1; s++) {
#pragma unroll
        for (int k = 0; k < 4; k++)
            cp16(stg_u32 + (uint32_t)(s * STAGE_FLOATS * 4 + 16 * tid + 8192 * k),
                 (const char*)xr + (size_t)s * 32768 + 16 * tid + 8192 * k);
        cp_commit();
    }

    // ---- Mainloop: 32 sequential 32 KB stages ----
    for (int s = 0; s < NST; ++s) {
        cp_wait<NSTAGE - 2>();
        __syncthreads();       // stage s visible; slot (s-1)&3 fully consumed

        const int jn = s + NSTAGE - 1;
        if (jn < NST) {
#pragma unroll
            for (int k = 0; k < 4; k++)
                cp16(stg_u32 + (uint32_t)((jn & 3) * STAGE_FLOATS * 4 + 16 * tid + 8192 * k),
                     (const char*)xr + (size_t)jn * 32768 + 16 * tid + 8192 * k);
        }
        cp_commit();

        const float* st = stg + (s & 3) * STAGE_FLOATS;
#pragma unroll
        for (int j = 0; j < 2; ++j) {
            const int tok = 2 * s + j;
            const float* tp = st + j * MODEL_DIM;

            const float4 xg0 = *(const float4*)(tp + 4 * tid);
            const float4 xg1 = *(const float4*)(tp + 2048 + 4 * tid);

            unsigned long long acc[NP] = {0ull, 0ull, 0ull, 0ull};
            const float* f0 = (const float*)&xg0;
            const float* f1 = (const float*)&xg1;
#pragma unroll
            for (int k = 0; k < 4; k++) {
                const unsigned long long xd0 = dup2(f0[k]);
                const unsigned long long xd1 = dup2(f1[k]);
#pragma unroll
                for (int p = 0; p < NP; p++) {
                    ffma2(acc[p], xd0, w0[k][p]);
                    ffma2(acc[p], xd1, w1[k][p]);
                }
            }

            // Butterfly over 32 lanes on packed pairs
#pragma unroll
            for (int off = 16; off > 0; off >>= 1) {
#pragma unroll
                for (int p = 0; p < NP; p++)
                    acc[p] = addf2(acc[p], __shfl_xor_sync(0xffffffffu, acc[p], off));
            }

            // Lanes 0..7 scatter one expert each into SMEM logits
            float f[NE];
#pragma unroll
            for (int p = 0; p < NP; p++) unpack2(acc[p], f[2 * p], f[2 * p + 1]);
            if (lane < NE) {
                float v = f[0];
#pragma unroll
                for (int e = 1; e < NE; e++) if (lane == e) v = f[e];
                atomicAdd(&logits[tok * NE + lane], v);
            }
        }
    }

    __syncthreads();   // all partial sums landed

    // ---- Epilogue: thread t < 64 owns CTA-local token t ----
    if (tid < TPB) {
        const int gt = blockIdx.x * TPB + tid;

        // Packed logit pairs from SMEM
        unsigned long long lgp[NP];
#pragma unroll
        for (int p = 0; p < NP; p++)
            lgp[p] = pack2(logits[tid * NE + 2 * p], logits[tid * NE + 2 * p + 1]);

        // Prompt tail: 64 dims x 8 experts, W-tail from SMEM (broadcast LDS)
        const float4* pr = (const float4*)(prompt + (size_t)gt * PROMPT_DIM);
#pragma unroll
        for (int i = 0; i < 16; i++) {
            const float4 pv = __ldg(pr + i);
            const float* pf = (const float*)&pv;
#pragma unroll
            for (int k = 0; k < 4; k++) {
                const unsigned long long xd = dup2(pf[k]);
                const int d = 4 * i + k;
#pragma unroll
                for (int p = 0; p < NP; p++)
                    ffma2(lgp[p], xd, wtailp[d * 4 + p]);
            }
        }

        float lg[NE];
#pragma unroll
        for (int p = 0; p < NP; p++) unpack2(lgp[p], lg[2 * p], lg[2 * p + 1]);
#pragma unroll
        for (int e = 0; e < NE; e++) lg[e] += __ldg(b + e);

        // Top-2 with first-index tie-break (matches jax.lax.top_k)
        int i0 = 0; float m0 = lg[0];
#pragma unroll
        for (int e = 1; e < NE; e++)
            if (lg[e] > m0) { m0 = lg[e]; i0 = e; }
        int i1 = -1; float m1 = -INFINITY;
#pragma unroll
        for (int e = 0; e < NE; e++)
            if (e != i0 && lg[e] > m1) { m1 = lg[e]; i1 = e; }

        float s = 0.0f;
#pragma unroll
        for (int e = 0; e < NE; e++) s += __expf(lg[e] - m0);
        const float g0 = 1.0f / s;
        const float g1 = __expf(m1 - m0) / s;
        const float denom = fmaxf(g0 + g1, 1.1920929e-07f);
        const float r0 = g0 / denom;
        const float r1 = g1 / denom;

        // masks: [T, 2, 8] at offset 0
        float* mrow = out + (size_t)gt * 16;
        const float4 z = make_float4(0.f, 0.f, 0.f, 0.f);
        *(float4*)(mrow + 0)  = z;
        *(float4*)(mrow + 4)  = z;
        *(float4*)(mrow + 8)  = z;
        *(float4*)(mrow + 12) = z;
        mrow[i0]     = 1.0f;
        mrow[8 + i1] = 1.0f;

        // gates_s: [T, 2] at offset T*16
        float* grow = out + (size_t)TOKENS * 16 + (size_t)gt * 2;
        grow[0] = r0;
        grow[1] = r1;
    }
}

extern "C" void kernel_launch(void* const* d_in, const int* in_sizes, int n_in,
                              void* d_out, int out_size)
{
    const float* x      = (const float*)d_in[0];
    const float* prompt = (const float*)d_in[1];
    const float* W      = (const float*)d_in[2];
    const float* b      = (const float*)d_in[3];
    float* out          = (float*)d_out;

    cudaFuncSetAttribute(topkgate_kernel,
                         cudaFuncAttributeMaxDynamicSharedMemorySize, SMEM_BYTES);

    topkgate_kernel<<<GRID, THREADS, SMEM_BYTES>>>(x, prompt, W, b, out);
}

// round 13
// speedup vs baseline: 1.7951x; 1.7951x over previous
#include <cuda_runtime.h>
#include <math.h>

#define TOKENS     8192
#define MODEL_DIM  4096
#define PROMPT_DIM 64
#define KTOT       (MODEL_DIM + PROMPT_DIM)   // 4160
#define NE         8
#define NP         4                          // expert pairs
#define TPW        4                          // tokens per warp
#define WARPS      16
#define TPB        (TPW * WARPS)              // 64 tokens per block
#define THREADS    512
#define GRID       (TOKENS / TPB)             // 128 CTAs, one wave
#define DSTRIDE    4162                       // per-pair row, float2 units
#define SMEM_BYTES (NP * DSTRIDE * 8)         // 133,184 B
#define CHUNK      128                        // dims per K-chunk (float4 per lane, 512B burst)
#define NIT        (MODEL_DIM / CHUNK)        // 32
#define RING       3                          // prefetch distance 2

// d = a*b + d elementwise on packed fp32x2
__device__ __forceinline__ void ffma2(unsigned long long& d,
                                      unsigned long long a,
                                      unsigned long long b) {
    asm("fma.rn.f32x2 %0, %1, %2, %0;" : "+l"(d) : "l"(a), "l"(b));
}
__device__ __forceinline__ unsigned long long dup2(float v) {
    unsigned long long r;
    asm("mov.b64 %0, {%1, %1};" : "=l"(r) : "f"(v));
    return r;
}
__device__ __forceinline__ void unpack2(unsigned long long v, float& lo, float& hi) {
    asm("mov.b64 {%0, %1}, %2;" : "=f"(lo), "=f"(hi) : "l"(v));
}

__global__ __launch_bounds__(THREADS, 1)
void topkgate_kernel(const float* __restrict__ x,
                     const float* __restrict__ prompt,
                     const float* __restrict__ W,
                     const float* __restrict__ b,
                     float* __restrict__ out)
{
    extern __shared__ float2 wsp[];   // wsp[p * DSTRIDE + d] = (W[d][2p], W[d][2p+1])

    const int tid   = threadIdx.x;
    const int w     = tid >> 5;
    const int lane  = tid & 31;
    const int tbase = blockIdx.x * TPB + w * TPW;   // grid covers TOKENS exactly

    // Single base pointer; per-token offsets folded into immediates/IMAD.
    const float* xb = x + (size_t)tbase * MODEL_DIM + 4 * lane;

    // ---- Ring prologue FIRST: x-load latency overlaps W staging below ----
    float4 buf[RING][TPW];
#pragma unroll
    for (int q = 0; q < RING - 1; q++)
#pragma unroll
        for (int m = 0; m < TPW; m++)
            buf[q][m] = __ldcs((const float4*)(xb + m * MODEL_DIM + q * CHUNK));

    // ---- Stage W into expert-paired SMEM layout ----
    {
        const float2* Wv = (const float2*)W;   // Wv[d*4 + p] = (W[d][2p], W[d][2p+1])
        for (int i = tid; i < KTOT * NP; i += THREADS) {
            int d = i >> 2;
            int p = i & 3;
            wsp[p * DSTRIDE + d] = Wv[i];
        }
    }
    __syncthreads();

    // Packed accumulators: acc[m][p] = (logit[2p], logit[2p+1]) partial sums
    unsigned long long acc[TPW][NP];
#pragma unroll
    for (int m = 0; m < TPW; m++)
#pragma unroll
        for (int p = 0; p < NP; p++) acc[m][p] = 0ull;

    // ---- Mainloop: 3-deep register ring, prefetch distance 2 ----
    for (int it = 0; it < NIT; it += RING) {
#pragma unroll
        for (int u = 0; u < RING; u++) {
            const int j = it + u;
            if (j < NIT) {
                // Prefetch chunk j+2 into ring slot (u+2)%3
                if (j + (RING - 1) < NIT) {
                    const int slot = (u + RING - 1) % RING;
#pragma unroll
                    for (int m = 0; m < TPW; m++)
                        buf[slot][m] = __ldcs(
                            (const float4*)(xb + m * MODEL_DIM + (j + RING - 1) * CHUNK));
                }

                // W slice: dims d0..d0+3 for 4 expert pairs — 8x LDS.128, conflict-free
                const int d0 = j * CHUNK + 4 * lane;
                ulonglong2 wv[NP][2];
#pragma unroll
                for (int p = 0; p < NP; p++) {
                    wv[p][0] = *(const ulonglong2*)&wsp[p * DSTRIDE + d0];      // dims d0, d0+1
                    wv[p][1] = *(const ulonglong2*)&wsp[p * DSTRIDE + d0 + 2];  // dims d0+2, d0+3
                }

#pragma unroll
                for (int m = 0; m < TPW; m++) {
                    const float4 xv = buf[u][m];
                    const unsigned long long x0 = dup2(xv.x);
                    const unsigned long long x1 = dup2(xv.y);
                    const unsigned long long x2 = dup2(xv.z);
                    const unsigned long long x3 = dup2(xv.w);
#pragma unroll
                    for (int p = 0; p < NP; p++) {
                        ffma2(acc[m][p], x0, wv[p][0].x);
                        ffma2(acc[m][p], x1, wv[p][0].y);
                        ffma2(acc[m][p], x2, wv[p][1].x);
                        ffma2(acc[m][p], x3, wv[p][1].y);
                    }
                }
            }
        }
    }

    // ---- Prompt tail: lane handles dims (4096+2*lane, +1) for all tokens ----
    {
        const int po = MODEL_DIM + 2 * lane;
        ulonglong2 wp[NP];
#pragma unroll
        for (int p = 0; p < NP; p++)
            wp[p] = *(const ulonglong2*)&wsp[p * DSTRIDE + po];
#pragma unroll
        for (int m = 0; m < TPW; m++) {
            const float2 pv = *(const float2*)(prompt + (size_t)(tbase + m) * PROMPT_DIM + 2 * lane);
            const unsigned long long plo = dup2(pv.x);
            const unsigned long long phi = dup2(pv.y);
#pragma unroll
            for (int p = 0; p < NP; p++) {
                ffma2(acc[m][p], plo, wp[p].x);
                ffma2(acc[m][p], phi, wp[p].y);
            }
        }
    }

    // ---- Unpack to scalar accumulators ----
    float accf[TPW][NE];
#pragma unroll
    for (int m = 0; m < TPW; m++)
#pragma unroll
        for (int p = 0; p < NP; p++)
            unpack2(acc[m][p], accf[m][2 * p], accf[m][2 * p + 1]);

    // ---- Warp butterfly reduction over lanes ----
#pragma unroll
    for (int off = 16; off > 0; off >>= 1) {
#pragma unroll
        for (int m = 0; m < TPW; m++)
#pragma unroll
            for (int e = 0; e < NE; e++)
                accf[m][e] += __shfl_xor_sync(0xffffffffu, accf[m][e], off);
    }

    // ---- Epilogue: lane m handles token (tbase + m) ----
    if (lane < TPW) {
        const int t = tbase + lane;

        float lg[NE];
#pragma unroll
        for (int m = 0; m < TPW; m++) {
            if (lane == m) {
#pragma unroll
                for (int e = 0; e < NE; e++) lg[e] = accf[m][e];
            }
        }
#pragma unroll
        for (int e = 0; e < NE; e++) lg[e] += b[e];

        // Top-2 with first-index tie-break (matches jax.lax.top_k)
        int i0 = 0; float m0 = lg[0];
#pragma unroll
        for (int e = 1; e < NE; e++)
            if (lg[e] > m0) { m0 = lg[e]; i0 = e; }
        int i1 = -1; float m1 = -INFINITY;
#pragma unroll
        for (int e = 0; e < NE; e++)
            if (e != i0 && lg[e] > m1) { m1 = lg[e]; i1 = e; }

        // Softmax over 8 (max-subtracted), gather top-2, renormalize with EPS clamp
        float s = 0.0f;
#pragma unroll
        for (int e = 0; e < NE; e++) s += __expf(lg[e] - m0);
        const float g0 = 1.0f / s;
        const float g1 = __expf(m1 - m0) / s;
        const float denom = fmaxf(g0 + g1, 1.1920929e-07f);
        const float r0 = g0 / denom;
        const float r1 = g1 / denom;

        // masks: [T, 2, 8] at offset 0
        float* mrow = out + (size_t)t * 16;
        const float4 z = make_float4(0.f, 0.f, 0.f, 0.f);
        *(float4*)(mrow + 0)  = z;
        *(float4*)(mrow + 4)  = z;
        *(float4*)(mrow + 8)  = z;
        *(float4*)(mrow + 12) = z;
        mrow[i0]     = 1.0f;
        mrow[8 + i1] = 1.0f;

        // gates_s: [T, 2] at offset T*16
        float* grow = out + (size_t)TOKENS * 16 + (size_t)t * 2;
        grow[0] = r0;
        grow[1] = r1;
    }
}

extern "C" void kernel_launch(void* const* d_in, const int* in_sizes, int n_in,
                              void* d_out, int out_size)
{
    const float* x      = (const float*)d_in[0];
    const float* prompt = (const float*)d_in[1];
    const float* W      = (const float*)d_in[2];
    const float* b      = (const float*)d_in[3];
    float* out          = (float*)d_out;

    cudaFuncSetAttribute(topkgate_kernel,
                         cudaFuncAttributeMaxDynamicSharedMemorySize, SMEM_BYTES);

    topkgate_kernel<<<GRID, THREADS, SMEM_BYTES>>>(x, prompt, W, b, out);
}